// round 10
// baseline (speedup 1.0000x reference)
#include <cuda_runtime.h>
#include <cuda_fp16.h>
#include <cstdint>

#define Bb   512
#define Tt   128
#define Ff   512
#define Hh   512
#define G3c  1536
#define MBIG (Bb * Tt)
#define BH   (Bb * Hh)

// ---------------------------------------------------------------------------
// Device-global scratch
// ---------------------------------------------------------------------------
__device__ float g_xproj[(size_t)MBIG * G3c];      // [T*B, 3H], m = t*B + b
__device__ float g_h[BH];                          // final hidden (fp32)
__device__ __half g_hh[2 * BH];                    // ping-pong h (fp16)
__device__ __half g_xh[(size_t)MBIG * Ff];         // x (fp16), [m, f]
__device__ __half g_wt[G3c * Ff];                  // kernel^T  [N=3H, K=F]
__device__ __half g_rt[G3c * Hh];                  // rkernel^T [N=3H, K=H]

__device__ unsigned g_done[8 * 16 * 32];           // flag per (group, colblock), 128B apart

// ---------------------------------------------------------------------------
// Helpers
// ---------------------------------------------------------------------------
__device__ __forceinline__ void mma16816(float* d, const uint32_t* a, const uint32_t* b) {
    asm volatile(
        "mma.sync.aligned.m16n8k16.row.col.f32.f16.f16.f32 "
        "{%0,%1,%2,%3}, {%4,%5,%6,%7}, {%8,%9}, {%0,%1,%2,%3};"
        : "+f"(d[0]), "+f"(d[1]), "+f"(d[2]), "+f"(d[3])
        : "r"(a[0]), "r"(a[1]), "r"(a[2]), "r"(a[3]), "r"(b[0]), "r"(b[1]));
}
__device__ __forceinline__ void ldmx4(uint32_t* r, uint32_t addr) {
    asm volatile("ldmatrix.sync.aligned.m8n8.x4.shared.b16 {%0,%1,%2,%3}, [%4];"
                 : "=r"(r[0]), "=r"(r[1]), "=r"(r[2]), "=r"(r[3]) : "r"(addr));
}
__device__ __forceinline__ void ldmx2(uint32_t* r, uint32_t addr) {
    asm volatile("ldmatrix.sync.aligned.m8n8.x2.shared.b16 {%0,%1}, [%2];"
                 : "=r"(r[0]), "=r"(r[1]) : "r"(addr));
}
__device__ __forceinline__ float sigm(float x) { return 1.0f / (1.0f + __expf(-x)); }
__device__ __forceinline__ float tanh_fast(float x) {
    return 1.0f - 2.0f / (__expf(2.0f * x) + 1.0f);
}
__device__ __forceinline__ uint32_t smem_u32(const void* p) {
    uint32_t a;
    asm("{ .reg .u64 t; cvta.to.shared.u64 t, %1; cvt.u32.u64 %0, t; }"
        : "=r"(a) : "l"(p));
    return a;
}
__device__ __forceinline__ void cp16(uint32_t s, const void* g) {
    asm volatile("cp.async.cg.shared.global [%0], [%1], 16;" :: "r"(s), "l"(g));
}
__device__ __forceinline__ void cp_commit() { asm volatile("cp.async.commit_group;"); }
template <int N>
__device__ __forceinline__ void cp_wait() {
    asm volatile("cp.async.wait_group %0;" :: "n"(N));
}
__device__ __forceinline__ unsigned ld_acq(const unsigned* p) {
    unsigned v;
    asm volatile("ld.acquire.gpu.global.u32 %0, [%1];" : "=r"(v) : "l"(p) : "memory");
    return v;
}
__device__ __forceinline__ void st_rel(unsigned* p, unsigned v) {
    asm volatile("st.release.gpu.global.u32 [%0], %1;" :: "l"(p), "r"(v) : "memory");
}
__device__ __forceinline__ void wait_ge(const unsigned* f, unsigned target) {
    while ((int)(ld_acq(f) - target) < 0) { __nanosleep(20); }
}

// ---------------------------------------------------------------------------
// Prep kernels
// ---------------------------------------------------------------------------
__global__ void prep_x_kernel(const float* __restrict__ x) {
    int m = blockIdx.x;
    int b = m & (Bb - 1);
    int t = m >> 9;
    const float4 v = ((const float4*)(x + ((size_t)b * Tt + t) * Ff))[threadIdx.x];
    size_t o = (size_t)m * Ff + threadIdx.x * 4;
    *(__half2*)(g_xh + o)     = __floats2half2_rn(v.x, v.y);
    *(__half2*)(g_xh + o + 2) = __floats2half2_rn(v.z, v.w);
}

__global__ void prep_w_kernel(const float* __restrict__ W, __half* __restrict__ out) {
    __shared__ float tile[32][33];
    const int nb = blockIdx.x * 32, kb = blockIdx.y * 32;
    const int tx = threadIdx.x, ty = threadIdx.y;
#pragma unroll
    for (int j = 0; j < 4; ++j)
        tile[ty + 8 * j][tx] = W[(size_t)(kb + ty + 8 * j) * G3c + nb + tx];
    __syncthreads();
#pragma unroll
    for (int j = 0; j < 4; ++j)
        out[(size_t)(nb + ty + 8 * j) * 512 + kb + tx] = __float2half(tile[tx][ty + 8 * j]);
}

// ---------------------------------------------------------------------------
// Input-projection GEMM, fp16 mma.sync + ldmatrix, 3-stage cp.async.
// BM=128, BN=128, BK=32, 256 threads, ONE __syncthreads per kb.
// ---------------------------------------------------------------------------
#define XP_PAD 40
#define XP_MAT (128 * XP_PAD)
#define XP_STAGE (2 * XP_MAT)
#define XP_SMEM (3 * XP_STAGE * 2)

__global__ void __launch_bounds__(256)
gemm_xproj(const __half* __restrict__ A,
           const __half* __restrict__ B,
           const float* __restrict__ bias,
           float* __restrict__ C)
{
    extern __shared__ __align__(128) char dsm[];
    const uint32_t sbase = smem_u32(dsm);

    const int tid = threadIdx.x;
    const int wid = tid >> 5, lane = tid & 31;
    const int wm = wid & 3;          // 4 warps over M
    const int wn = wid >> 2;         // 2 warps over N
    const int m0 = blockIdx.y * 128, n0 = blockIdx.x * 128;

    const int sr = tid >> 2, sc = tid & 3;

    uint32_t a_off[2], b_off[4];
#pragma unroll
    for (int mt = 0; mt < 2; ++mt)
        a_off[mt] = (uint32_t)((wm * 32 + mt * 16 + (lane & 15)) * XP_PAD + (lane >> 4) * 8);
#pragma unroll
    for (int p = 0; p < 4; ++p)
        b_off[p] = (uint32_t)((wn * 64 + p * 16 + (lane >> 4) * 8 + (lane & 7)) * XP_PAD
                              + ((lane & 8) ? 8 : 0));

    float acc[2][8][4];
#pragma unroll
    for (int i = 0; i < 2; ++i)
#pragma unroll
        for (int j = 0; j < 8; ++j)
#pragma unroll
            for (int q = 0; q < 4; ++q) acc[i][j][q] = 0.0f;

    auto stage_load = [&](int kb, int st) {
        const int k0 = kb * 32;
        const uint32_t sb = sbase + st * (XP_STAGE * 2);
#pragma unroll
        for (int it = 0; it < 2; ++it) {
            int r = it * 64 + sr;
            uint32_t so = (uint32_t)(r * XP_PAD + sc * 8) * 2;
            cp16(sb + so,              A + (size_t)(m0 + r) * 512 + k0 + sc * 8);
            cp16(sb + XP_MAT * 2 + so, B + (size_t)(n0 + r) * 512 + k0 + sc * 8);
        }
        cp_commit();
    };

    stage_load(0, 0);
    stage_load(1, 1);

    int st = 0;
    for (int kb = 0; kb < 16; ++kb) {
        if (kb < 15) cp_wait<1>(); else cp_wait<0>();
        __syncthreads();

        const uint32_t stb = sbase + st * (XP_STAGE * 2);

#pragma unroll
        for (int ks = 0; ks < 2; ++ks) {
            const uint32_t ko2 = (uint32_t)(ks * 16) * 2;
            uint32_t ah[2][4], bh[8][2];
#pragma unroll
            for (int mt = 0; mt < 2; ++mt)
                ldmx4(ah[mt], stb + a_off[mt] * 2 + ko2);
#pragma unroll
            for (int p = 0; p < 4; ++p) {
                uint32_t r4[4];
                ldmx4(r4, stb + XP_MAT * 2 + b_off[p] * 2 + ko2);
                bh[2 * p][0] = r4[0]; bh[2 * p][1] = r4[1];
                bh[2 * p + 1][0] = r4[2]; bh[2 * p + 1][1] = r4[3];
            }
#pragma unroll
            for (int mt = 0; mt < 2; ++mt)
#pragma unroll
                for (int nt = 0; nt < 8; ++nt)
                    mma16816(acc[mt][nt], ah[mt], bh[nt]);
        }

        if (kb < 14) {
            int ns = st + 2; if (ns >= 3) ns -= 3;
            stage_load(kb + 2, ns);
        }
        ++st; if (st == 3) st = 0;
    }

#pragma unroll
    for (int mt = 0; mt < 2; ++mt) {
#pragma unroll
        for (int nt = 0; nt < 8; ++nt) {
            int n = n0 + wn * 64 + nt * 8 + (lane & 3) * 2;
            int mA = m0 + wm * 32 + mt * 16 + (lane >> 2);
            int mB = mA + 8;
            float bx = bias[n], by = bias[n + 1];
            float2 o0 = make_float2(acc[mt][nt][0] + bx, acc[mt][nt][1] + by);
            float2 o1 = make_float2(acc[mt][nt][2] + bx, acc[mt][nt][3] + by);
            *(float2*)(C + (size_t)mA * G3c + n) = o0;
            *(float2*)(C + (size_t)mB * G3c + n) = o1;
        }
    }
}

// ---------------------------------------------------------------------------
// Persistent fused recurrence: fp16, ldmatrix, BK=64, fine-grained
// producer/consumer flags (no bulk barrier). Grid (16, 8).
// Chunk kb (K in [64kb,64kb+64)) depends only on producers 2kb, 2kb+1.
// ---------------------------------------------------------------------------
#define PAD_A 72
#define PAD_B 520
#define SB_ELEMS (96 * PAD_B)
#define SA_ELEMS (64 * PAD_A)
#define SMEM_PERSIST ((SB_ELEMS + 4 * SA_ELEMS) * 2)

__global__ void __launch_bounds__(256)
gru_persistent(const float* __restrict__ bias_r)
{
    extern __shared__ __align__(128) char smem[];
    __half* sB = (__half*)smem;
    __half* sA = sB + SB_ELEMS;            // 4 stages x SA_ELEMS
    const uint32_t sB_base = smem_u32(sB);
    const uint32_t sA_base = smem_u32(sA);

    const int tid  = threadIdx.x;
    const int wid  = tid >> 5, lane = tid & 31;
    const int wm   = wid & 1;
    const int wn   = wid >> 1;
    const int lr   = lane >> 2;
    const int lc   = (lane & 3) * 2;
    const int n0   = blockIdx.x * 32;
    const int m0   = blockIdx.y * 64;
    const int grp  = blockIdx.y;

    // resident B tile: 96 interleaved rows x 512 cols (fp16)
    for (int idx = tid; idx < 96 * 64; idx += 256) {
        int rr = idx >> 6, c4 = idx & 63;
        int wq = rr / 24, rem = rr % 24;
        int g = rem >> 3, s = rem & 7;
        size_t grow = (size_t)(g * 512 + n0 + wq * 8 + s) * 512 + c4 * 8;
        *(uint4*)&sB[rr * PAD_B + c4 * 8] = *(const uint4*)(g_rt + grow);
    }

    uint32_t a_off[2];
#pragma unroll
    for (int mt = 0; mt < 2; ++mt)
        a_off[mt] = (uint32_t)((wm * 32 + mt * 16 + (lane & 15)) * PAD_A + (lane >> 4) * 8);
    const uint32_t b_off01 = (uint32_t)((wn * 24 + (lane >> 4) * 8 + (lane & 7)) * PAD_B
                                        + ((lane & 8) ? 8 : 0));
    const uint32_t b_off2  = (uint32_t)((wn * 24 + 16 + (lane & 7)) * PAD_B
                                        + ((lane & 8) ? 8 : 0));

    const int c0g = n0 + wn * 8 + lc;
    const float2 brz = *(const float2*)(bias_r + c0g);
    const float2 brr = *(const float2*)(bias_r + 512 + c0g);
    const float2 brh = *(const float2*)(bias_r + 1024 + c0g);

    float hprev[2][2][2];
#pragma unroll
    for (int a = 0; a < 2; ++a)
#pragma unroll
        for (int b = 0; b < 2; ++b) { hprev[a][b][0] = 0.0f; hprev[a][b][1] = 0.0f; }

    float acc[2][3][4];
#pragma unroll
    for (int a = 0; a < 2; ++a)
#pragma unroll
        for (int g = 0; g < 3; ++g)
#pragma unroll
            for (int q = 0; q < 4; ++q) acc[a][g][q] = 0.0f;

    // A staging: 64 rows x 64 halves = 512 16B-chunks, 2 per thread
    const int ar0 = tid >> 3, ac0 = tid & 7;
    const int ar1 = (tid + 256) >> 3, ac1 = (tid + 256) & 7;
    const uint32_t soA0 = (uint32_t)(ar0 * PAD_A + ac0 * 8) * 2;
    const uint32_t soA1 = (uint32_t)(ar1 * PAD_A + ac1 * 8) * 2;

    unsigned* myflag = &g_done[(grp * 16 + blockIdx.x) * 32];
    const unsigned base = *(volatile unsigned*)myflag;

    __syncthreads();

#pragma unroll 1
    for (int t = 0; t < Tt; ++t) {
        const int cur = t & 1, nxt = cur ^ 1;

        // register-prefetch xproj operands (independent of h)
        const float* xr = g_xproj + (size_t)t * Bb * G3c;
        float2 xp[2][2][3];
#pragma unroll
        for (int mt = 0; mt < 2; ++mt)
#pragma unroll
            for (int rp = 0; rp < 2; ++rp) {
                int row = m0 + wm * 32 + mt * 16 + lr + rp * 8;
                const float* xrow = xr + (size_t)row * G3c + c0g;
                xp[mt][rp][0] = __ldcg((const float2*)(xrow));
                xp[mt][rp][1] = __ldcg((const float2*)(xrow + 512));
                xp[mt][rp][2] = __ldcg((const float2*)(xrow + 1024));
            }

        if (t > 0) {
            const unsigned tgt = base + (unsigned)t;   // h(t) published by step t-1
            const __half* Ah = g_hh + (size_t)cur * BH;

            // prefetch chunks 0,1 into stages 0,1 (flag-gated per chunk)
#pragma unroll
            for (int pk = 0; pk < 2; ++pk) {
                if (lane < 2) wait_ge(&g_done[(grp * 16 + 2 * pk + lane) * 32], tgt);
                __syncwarp();
                const uint32_t sb = sA_base + (uint32_t)(pk * SA_ELEMS) * 2;
                cp16(sb + soA0, Ah + (size_t)(m0 + ar0) * 512 + pk * 64 + ac0 * 8);
                cp16(sb + soA1, Ah + (size_t)(m0 + ar1) * 512 + pk * 64 + ac1 * 8);
                cp_commit();
            }

#pragma unroll 1
            for (int kb = 0; kb < 8; ++kb) {
                const int st = kb & 3;
                if (kb < 6) {
                    const int c = kb + 2;
                    if (lane < 2) wait_ge(&g_done[(grp * 16 + 2 * c + lane) * 32], tgt);
                    __syncwarp();
                    const uint32_t sb = sA_base + (uint32_t)((c & 3) * SA_ELEMS) * 2;
                    cp16(sb + soA0, Ah + (size_t)(m0 + ar0) * 512 + c * 64 + ac0 * 8);
                    cp16(sb + soA1, Ah + (size_t)(m0 + ar1) * 512 + c * 64 + ac1 * 8);
                    cp_commit();
                    cp_wait<2>();
                } else if (kb == 6) {
                    cp_wait<1>();
                } else {
                    cp_wait<0>();
                }
                __syncthreads();

                const uint32_t stb = sA_base + (uint32_t)(st * SA_ELEMS) * 2;
                const uint32_t kb2 = (uint32_t)(kb * 64) * 2;

#pragma unroll
                for (int ks = 0; ks < 4; ++ks) {
                    const uint32_t ko2 = (uint32_t)(ks * 16) * 2;
                    uint32_t ah[2][4], bh[3][2];
#pragma unroll
                    for (int mt = 0; mt < 2; ++mt)
                        ldmx4(ah[mt], stb + a_off[mt] * 2 + ko2);
                    {
                        uint32_t r4[4];
                        ldmx4(r4, sB_base + b_off01 * 2 + kb2 + ko2);
                        bh[0][0] = r4[0]; bh[0][1] = r4[1];
                        bh[1][0] = r4[2]; bh[1][1] = r4[3];
                        ldmx2(bh[2], sB_base + b_off2 * 2 + kb2 + ko2);
                    }
#pragma unroll
                    for (int mt = 0; mt < 2; ++mt)
#pragma unroll
                        for (int g = 0; g < 3; ++g)
                            mma16816(acc[mt][g], ah[mt], bh[g]);
                }
            }
        }

        // ---- fused gate epilogue (registers only) ----
#pragma unroll
        for (int mt = 0; mt < 2; ++mt) {
#pragma unroll
            for (int rp = 0; rp < 2; ++rp) {
                int row = m0 + wm * 32 + mt * 16 + lr + rp * 8;
                float2 xz = xp[mt][rp][0];
                float2 xg = xp[mt][rp][1];
                float2 xh = xp[mt][rp][2];

                float hpz0 = acc[mt][0][rp * 2 + 0] + brz.x;
                float hpz1 = acc[mt][0][rp * 2 + 1] + brz.y;
                float hpr0 = acc[mt][1][rp * 2 + 0] + brr.x;
                float hpr1 = acc[mt][1][rp * 2 + 1] + brr.y;
                float hph0 = acc[mt][2][rp * 2 + 0] + brh.x;
                float hph1 = acc[mt][2][rp * 2 + 1] + brh.y;

                float z0 = sigm(xz.x + hpz0), r0 = sigm(xg.x + hpr0);
                float c0 = tanh_fast(xh.x + r0 * hph0);
                float h0 = z0 * hprev[mt][rp][0] + (1.0f - z0) * c0;
                float z1 = sigm(xz.y + hpz1), r1 = sigm(xg.y + hpr1);
                float c1 = tanh_fast(xh.y + r1 * hph1);
                float h1 = z1 * hprev[mt][rp][1] + (1.0f - z1) * c1;

                hprev[mt][rp][0] = h0;
                hprev[mt][rp][1] = h1;

                size_t oo = (size_t)nxt * BH + (size_t)row * 512 + c0g;
                __stcg((__half2*)(g_hh + oo), __floats2half2_rn(h0, h1));

                acc[mt][0][rp * 2] = 0.0f; acc[mt][0][rp * 2 + 1] = 0.0f;
                acc[mt][1][rp * 2] = 0.0f; acc[mt][1][rp * 2 + 1] = 0.0f;
                acc[mt][2][rp * 2] = 0.0f; acc[mt][2][rp * 2 + 1] = 0.0f;
            }
        }

        // publish own columns of h(t+1)
        __threadfence();
        __syncthreads();
        if (tid == 0) st_rel(myflag, base + (unsigned)(t + 1));
    }

    // final h (fp32) for the dense head
#pragma unroll
    for (int mt = 0; mt < 2; ++mt)
#pragma unroll
        for (int rp = 0; rp < 2; ++rp) {
            int row = m0 + wm * 32 + mt * 16 + lr + rp * 8;
            *(float2*)(g_h + (size_t)row * 512 + c0g) =
                make_float2(hprev[mt][rp][0], hprev[mt][rp][1]);
        }
}

// ---------------------------------------------------------------------------
// Dense head
// ---------------------------------------------------------------------------
__global__ void dense_kernel(const float* __restrict__ w,
                             const float* __restrict__ b0,
                             float* __restrict__ out)
{
    __shared__ float red[4];
    int b = blockIdx.x;
    int tid = threadIdx.x;
    const float* hrow = g_h + (size_t)b * Hh;

    float s = 0.0f;
    for (int n = tid; n < Hh; n += 128) s = fmaf(hrow[n], w[n], s);
#pragma unroll
    for (int o = 16; o > 0; o >>= 1) s += __shfl_down_sync(0xffffffffu, s, o);
    if ((tid & 31) == 0) red[tid >> 5] = s;
    __syncthreads();
    if (tid == 0) out[b] = red[0] + red[1] + red[2] + red[3] + b0[0];
}

// ---------------------------------------------------------------------------
// Launch
// ---------------------------------------------------------------------------
extern "C" void kernel_launch(void* const* d_in, const int* in_sizes, int n_in,
                              void* d_out, int out_size)
{
    const float* x       = (const float*)d_in[0];
    const float* kernel  = (const float*)d_in[1];
    const float* rkernel = (const float*)d_in[2];
    const float* bias_i  = (const float*)d_in[3];
    const float* bias_r  = (const float*)d_in[4];
    const float* dense_w = (const float*)d_in[5];
    const float* dense_b = (const float*)d_in[6];
    float* out = (float*)d_out;

    void *p_xh, *p_wt, *p_rt, *p_xproj;
    cudaGetSymbolAddress(&p_xh, g_xh);
    cudaGetSymbolAddress(&p_wt, g_wt);
    cudaGetSymbolAddress(&p_rt, g_rt);
    cudaGetSymbolAddress(&p_xproj, g_xproj);

    static bool attr_set = false;
    if (!attr_set) {
        cudaFuncSetAttribute(gru_persistent,
                             cudaFuncAttributeMaxDynamicSharedMemorySize, SMEM_PERSIST);
        cudaFuncSetAttribute(gemm_xproj,
                             cudaFuncAttributeMaxDynamicSharedMemorySize, XP_SMEM);
        attr_set = true;
    }

    prep_x_kernel<<<MBIG, 128>>>(x);
    prep_w_kernel<<<dim3(48, 16), dim3(32, 8)>>>(kernel,  (__half*)p_wt);
    prep_w_kernel<<<dim3(48, 16), dim3(32, 8)>>>(rkernel, (__half*)p_rt);

    gemm_xproj<<<dim3(G3c / 128, MBIG / 128), 256, XP_SMEM>>>(
        (const __half*)p_xh, (const __half*)p_wt, bias_i, (float*)p_xproj);

    gru_persistent<<<dim3(16, 8), 256, SMEM_PERSIST>>>(bias_r);

    dense_kernel<<<Bb, 128>>>(dense_w, dense_b, out);
}

// round 11
// speedup vs baseline: 1.2343x; 1.2343x over previous
#include <cuda_runtime.h>
#include <cuda_fp16.h>
#include <cstdint>

#define Bb   512
#define Tt   128
#define Ff   512
#define Hh   512
#define G3c  1536
#define MBIG (Bb * Tt)
#define BH   (Bb * Hh)

// ---------------------------------------------------------------------------
// Device-global scratch
// ---------------------------------------------------------------------------
__device__ float g_xproj[(size_t)MBIG * G3c];      // [T*B, 3H], m = t*B + b
__device__ float g_h[BH];                          // final hidden (fp32)
__device__ __half g_hh[2 * BH];                    // ping-pong h (fp16)
__device__ __half g_xh[(size_t)MBIG * Ff];         // x (fp16), [m, f]
__device__ __half g_wt[G3c * Ff];                  // kernel^T  [N=3H, K=F]
__device__ __half g_rt[G3c * Hh];                  // rkernel^T [N=3H, K=H]

__device__ unsigned g_done[8 * 16 * 32];           // flag per (group, colblock), 128B apart

// ---------------------------------------------------------------------------
// Helpers
// ---------------------------------------------------------------------------
__device__ __forceinline__ void mma16816(float* d, const uint32_t* a, const uint32_t* b) {
    asm volatile(
        "mma.sync.aligned.m16n8k16.row.col.f32.f16.f16.f32 "
        "{%0,%1,%2,%3}, {%4,%5,%6,%7}, {%8,%9}, {%0,%1,%2,%3};"
        : "+f"(d[0]), "+f"(d[1]), "+f"(d[2]), "+f"(d[3])
        : "r"(a[0]), "r"(a[1]), "r"(a[2]), "r"(a[3]), "r"(b[0]), "r"(b[1]));
}
__device__ __forceinline__ void ldmx4(uint32_t* r, uint32_t addr) {
    asm volatile("ldmatrix.sync.aligned.m8n8.x4.shared.b16 {%0,%1,%2,%3}, [%4];"
                 : "=r"(r[0]), "=r"(r[1]), "=r"(r[2]), "=r"(r[3]) : "r"(addr));
}
__device__ __forceinline__ void ldmx2(uint32_t* r, uint32_t addr) {
    asm volatile("ldmatrix.sync.aligned.m8n8.x2.shared.b16 {%0,%1}, [%2];"
                 : "=r"(r[0]), "=r"(r[1]) : "r"(addr));
}
__device__ __forceinline__ float sigm(float x) { return 1.0f / (1.0f + __expf(-x)); }
__device__ __forceinline__ float tanh_fast(float x) {
    return 1.0f - 2.0f / (__expf(2.0f * x) + 1.0f);
}
__device__ __forceinline__ uint32_t smem_u32(const void* p) {
    uint32_t a;
    asm("{ .reg .u64 t; cvta.to.shared.u64 t, %1; cvt.u32.u64 %0, t; }"
        : "=r"(a) : "l"(p));
    return a;
}
__device__ __forceinline__ void cp16(uint32_t s, const void* g) {
    asm volatile("cp.async.cg.shared.global [%0], [%1], 16;" :: "r"(s), "l"(g));
}
__device__ __forceinline__ void cp_commit() { asm volatile("cp.async.commit_group;"); }
template <int N>
__device__ __forceinline__ void cp_wait() {
    asm volatile("cp.async.wait_group %0;" :: "n"(N));
}

// ---------------------------------------------------------------------------
// Prep kernels
// ---------------------------------------------------------------------------
__global__ void prep_x_kernel(const float* __restrict__ x) {
    int m = blockIdx.x;
    int b = m & (Bb - 1);
    int t = m >> 9;
    const float4 v = ((const float4*)(x + ((size_t)b * Tt + t) * Ff))[threadIdx.x];
    size_t o = (size_t)m * Ff + threadIdx.x * 4;
    *(__half2*)(g_xh + o)     = __floats2half2_rn(v.x, v.y);
    *(__half2*)(g_xh + o + 2) = __floats2half2_rn(v.z, v.w);
}

__global__ void prep_w_kernel(const float* __restrict__ W, __half* __restrict__ out) {
    __shared__ float tile[32][33];
    const int nb = blockIdx.x * 32, kb = blockIdx.y * 32;
    const int tx = threadIdx.x, ty = threadIdx.y;
#pragma unroll
    for (int j = 0; j < 4; ++j)
        tile[ty + 8 * j][tx] = W[(size_t)(kb + ty + 8 * j) * G3c + nb + tx];
    __syncthreads();
#pragma unroll
    for (int j = 0; j < 4; ++j)
        out[(size_t)(nb + ty + 8 * j) * 512 + kb + tx] = __float2half(tile[tx][ty + 8 * j]);
}

// ---------------------------------------------------------------------------
// Input-projection GEMM, fp16 mma.sync + ldmatrix, 3-stage cp.async.
// BM=128, BN=128, BK=32, 256 threads, one __syncthreads per kb. (R10, kept)
// ---------------------------------------------------------------------------
#define XP_PAD 40
#define XP_MAT (128 * XP_PAD)
#define XP_STAGE (2 * XP_MAT)
#define XP_SMEM (3 * XP_STAGE * 2)

__global__ void __launch_bounds__(256)
gemm_xproj(const __half* __restrict__ A,
           const __half* __restrict__ B,
           const float* __restrict__ bias,
           float* __restrict__ C)
{
    extern __shared__ __align__(128) char dsm[];
    const uint32_t sbase = smem_u32(dsm);

    const int tid = threadIdx.x;
    const int wid = tid >> 5, lane = tid & 31;
    const int wm = wid & 3;
    const int wn = wid >> 2;
    const int m0 = blockIdx.y * 128, n0 = blockIdx.x * 128;

    const int sr = tid >> 2, sc = tid & 3;

    uint32_t a_off[2], b_off[4];
#pragma unroll
    for (int mt = 0; mt < 2; ++mt)
        a_off[mt] = (uint32_t)((wm * 32 + mt * 16 + (lane & 15)) * XP_PAD + (lane >> 4) * 8);
#pragma unroll
    for (int p = 0; p < 4; ++p)
        b_off[p] = (uint32_t)((wn * 64 + p * 16 + (lane >> 4) * 8 + (lane & 7)) * XP_PAD
                              + ((lane & 8) ? 8 : 0));

    float acc[2][8][4];
#pragma unroll
    for (int i = 0; i < 2; ++i)
#pragma unroll
        for (int j = 0; j < 8; ++j)
#pragma unroll
            for (int q = 0; q < 4; ++q) acc[i][j][q] = 0.0f;

    auto stage_load = [&](int kb, int st) {
        const int k0 = kb * 32;
        const uint32_t sb = sbase + st * (XP_STAGE * 2);
#pragma unroll
        for (int it = 0; it < 2; ++it) {
            int r = it * 64 + sr;
            uint32_t so = (uint32_t)(r * XP_PAD + sc * 8) * 2;
            cp16(sb + so,              A + (size_t)(m0 + r) * 512 + k0 + sc * 8);
            cp16(sb + XP_MAT * 2 + so, B + (size_t)(n0 + r) * 512 + k0 + sc * 8);
        }
        cp_commit();
    };

    stage_load(0, 0);
    stage_load(1, 1);

    int st = 0;
    for (int kb = 0; kb < 16; ++kb) {
        if (kb < 15) cp_wait<1>(); else cp_wait<0>();
        __syncthreads();

        const uint32_t stb = sbase + st * (XP_STAGE * 2);

#pragma unroll
        for (int ks = 0; ks < 2; ++ks) {
            const uint32_t ko2 = (uint32_t)(ks * 16) * 2;
            uint32_t ah[2][4], bh[8][2];
#pragma unroll
            for (int mt = 0; mt < 2; ++mt)
                ldmx4(ah[mt], stb + a_off[mt] * 2 + ko2);
#pragma unroll
            for (int p = 0; p < 4; ++p) {
                uint32_t r4[4];
                ldmx4(r4, stb + XP_MAT * 2 + b_off[p] * 2 + ko2);
                bh[2 * p][0] = r4[0]; bh[2 * p][1] = r4[1];
                bh[2 * p + 1][0] = r4[2]; bh[2 * p + 1][1] = r4[3];
            }
#pragma unroll
            for (int mt = 0; mt < 2; ++mt)
#pragma unroll
                for (int nt = 0; nt < 8; ++nt)
                    mma16816(acc[mt][nt], ah[mt], bh[nt]);
        }

        if (kb < 14) {
            int ns = st + 2; if (ns >= 3) ns -= 3;
            stage_load(kb + 2, ns);
        }
        ++st; if (st == 3) st = 0;
    }

#pragma unroll
    for (int mt = 0; mt < 2; ++mt) {
#pragma unroll
        for (int nt = 0; nt < 8; ++nt) {
            int n = n0 + wn * 64 + nt * 8 + (lane & 3) * 2;
            int mA = m0 + wm * 32 + mt * 16 + (lane >> 2);
            int mB = mA + 8;
            float bx = bias[n], by = bias[n + 1];
            float2 o0 = make_float2(acc[mt][nt][0] + bx, acc[mt][nt][1] + by);
            float2 o1 = make_float2(acc[mt][nt][2] + bx, acc[mt][nt][3] + by);
            *(float2*)(C + (size_t)mA * G3c + n) = o0;
            *(float2*)(C + (size_t)mB * G3c + n) = o1;
        }
    }
}

// ---------------------------------------------------------------------------
// Persistent fused recurrence: fp16, ldmatrix, FULL 64x512 A tile staged per
// step in one cp.async burst, bulk per-group flag barrier (R9). Grid (16, 8).
// ---------------------------------------------------------------------------
#define PAD_AF 520
#define PAD_B 520
#define SB_ELEMS (96 * PAD_B)
#define SAF_ELEMS (64 * PAD_AF)
#define SMEM_PERSIST ((SB_ELEMS + SAF_ELEMS) * 2)

__global__ void __launch_bounds__(256)
gru_persistent(const float* __restrict__ bias_r)
{
    extern __shared__ __align__(128) char smem[];
    __half* sB = (__half*)smem;
    __half* sA = sB + SB_ELEMS;
    const uint32_t sB_base = smem_u32(sB);
    const uint32_t sA_base = smem_u32(sA);

    const int tid  = threadIdx.x;
    const int wid  = tid >> 5, lane = tid & 31;
    const int wm   = wid & 1;
    const int wn   = wid >> 1;
    const int lr   = lane >> 2;
    const int lc   = (lane & 3) * 2;
    const int n0   = blockIdx.x * 32;
    const int m0   = blockIdx.y * 64;
    const int grp  = blockIdx.y;

    // resident B tile: 96 interleaved rows x 512 cols (fp16)
    for (int idx = tid; idx < 96 * 64; idx += 256) {
        int rr = idx >> 6, c4 = idx & 63;
        int wq = rr / 24, rem = rr % 24;
        int g = rem >> 3, s = rem & 7;
        size_t grow = (size_t)(g * 512 + n0 + wq * 8 + s) * 512 + c4 * 8;
        *(uint4*)&sB[rr * PAD_B + c4 * 8] = *(const uint4*)(g_rt + grow);
    }

    uint32_t a_off[2];
#pragma unroll
    for (int mt = 0; mt < 2; ++mt)
        a_off[mt] = (uint32_t)((wm * 32 + mt * 16 + (lane & 15)) * PAD_AF + (lane >> 4) * 8);
    const uint32_t b_off01 = (uint32_t)((wn * 24 + (lane >> 4) * 8 + (lane & 7)) * PAD_B
                                        + ((lane & 8) ? 8 : 0));
    const uint32_t b_off2  = (uint32_t)((wn * 24 + 16 + (lane & 7)) * PAD_B
                                        + ((lane & 8) ? 8 : 0));

    const int c0g = n0 + wn * 8 + lc;
    const float2 brz = *(const float2*)(bias_r + c0g);
    const float2 brr = *(const float2*)(bias_r + 512 + c0g);
    const float2 brh = *(const float2*)(bias_r + 1024 + c0g);

    float hprev[2][2][2];
#pragma unroll
    for (int a = 0; a < 2; ++a)
#pragma unroll
        for (int b = 0; b < 2; ++b) { hprev[a][b][0] = 0.0f; hprev[a][b][1] = 0.0f; }

    float acc[2][3][4];
#pragma unroll
    for (int a = 0; a < 2; ++a)
#pragma unroll
        for (int g = 0; g < 3; ++g)
#pragma unroll
            for (int q = 0; q < 4; ++q) acc[a][g][q] = 0.0f;

    unsigned* myflag = &g_done[(grp * 16 + blockIdx.x) * 32];
    const unsigned base = *(volatile unsigned*)myflag;

    __syncthreads();

#pragma unroll 1
    for (int t = 0; t < Tt; ++t) {
        const int cur = t & 1, nxt = cur ^ 1;

        // register-prefetch xproj operands (independent of h)
        const float* xr = g_xproj + (size_t)t * Bb * G3c;
        float2 xp[2][2][3];
#pragma unroll
        for (int mt = 0; mt < 2; ++mt)
#pragma unroll
            for (int rp = 0; rp < 2; ++rp) {
                int row = m0 + wm * 32 + mt * 16 + lr + rp * 8;
                const float* xrow = xr + (size_t)row * G3c + c0g;
                xp[mt][rp][0] = __ldcg((const float2*)(xrow));
                xp[mt][rp][1] = __ldcg((const float2*)(xrow + 512));
                xp[mt][rp][2] = __ldcg((const float2*)(xrow + 1024));
            }

        if (t > 0) {
            const __half* Ah = g_hh + (size_t)cur * BH;

            // one burst: full 64x512 h tile -> smem (4096 chunks, 16/thread)
#pragma unroll
            for (int i = 0; i < 16; ++i) {
                int idx = i * 256 + tid;
                int r = idx >> 6, c = idx & 63;
                cp16(sA_base + (uint32_t)(r * PAD_AF + c * 8) * 2,
                     Ah + (size_t)(m0 + r) * 512 + c * 8);
            }
            cp_commit();
            cp_wait<0>();
            __syncthreads();

#pragma unroll 1
            for (int kb = 0; kb < 8; ++kb) {
                const uint32_t kb2 = (uint32_t)(kb * 64) * 2;
#pragma unroll
                for (int ks = 0; ks < 4; ++ks) {
                    const uint32_t ko2 = (uint32_t)(ks * 16) * 2;
                    uint32_t ah[2][4], bh[3][2];
#pragma unroll
                    for (int mt = 0; mt < 2; ++mt)
                        ldmx4(ah[mt], sA_base + a_off[mt] * 2 + kb2 + ko2);
                    {
                        uint32_t r4[4];
                        ldmx4(r4, sB_base + b_off01 * 2 + kb2 + ko2);
                        bh[0][0] = r4[0]; bh[0][1] = r4[1];
                        bh[1][0] = r4[2]; bh[1][1] = r4[3];
                        ldmx2(bh[2], sB_base + b_off2 * 2 + kb2 + ko2);
                    }
#pragma unroll
                    for (int mt = 0; mt < 2; ++mt)
#pragma unroll
                        for (int g = 0; g < 3; ++g)
                            mma16816(acc[mt][g], ah[mt], bh[g]);
                }
            }
            __syncthreads();
        }

        // ---- fused gate epilogue (registers only) ----
#pragma unroll
        for (int mt = 0; mt < 2; ++mt) {
#pragma unroll
            for (int rp = 0; rp < 2; ++rp) {
                int row = m0 + wm * 32 + mt * 16 + lr + rp * 8;
                float2 xz = xp[mt][rp][0];
                float2 xg = xp[mt][rp][1];
                float2 xh = xp[mt][rp][2];

                float hpz0 = acc[mt][0][rp * 2 + 0] + brz.x;
                float hpz1 = acc[mt][0][rp * 2 + 1] + brz.y;
                float hpr0 = acc[mt][1][rp * 2 + 0] + brr.x;
                float hpr1 = acc[mt][1][rp * 2 + 1] + brr.y;
                float hph0 = acc[mt][2][rp * 2 + 0] + brh.x;
                float hph1 = acc[mt][2][rp * 2 + 1] + brh.y;

                float z0 = sigm(xz.x + hpz0), r0 = sigm(xg.x + hpr0);
                float c0 = tanh_fast(xh.x + r0 * hph0);
                float h0 = z0 * hprev[mt][rp][0] + (1.0f - z0) * c0;
                float z1 = sigm(xz.y + hpz1), r1 = sigm(xg.y + hpr1);
                float c1 = tanh_fast(xh.y + r1 * hph1);
                float h1 = z1 * hprev[mt][rp][1] + (1.0f - z1) * c1;

                hprev[mt][rp][0] = h0;
                hprev[mt][rp][1] = h1;

                size_t oo = (size_t)nxt * BH + (size_t)row * 512 + c0g;
                __stcg((__half2*)(g_hh + oo), __floats2half2_rn(h0, h1));

                acc[mt][0][rp * 2] = 0.0f; acc[mt][0][rp * 2 + 1] = 0.0f;
                acc[mt][1][rp * 2] = 0.0f; acc[mt][1][rp * 2 + 1] = 0.0f;
                acc[mt][2][rp * 2] = 0.0f; acc[mt][2][rp * 2 + 1] = 0.0f;
            }
        }

        // ---- per-group bulk flag barrier (R9 style) ----
        __syncthreads();
        if (wid == 0) {
            const unsigned target = base + (unsigned)(t + 1);
            if (lane == 0) {
                __threadfence();
                *(volatile unsigned*)myflag = target;
            }
            if (lane < 16) {
                volatile unsigned* slot = &g_done[(grp * 16 + lane) * 32];
                while ((int)(*slot - target) < 0) { __nanosleep(20); }
                __threadfence();
            }
        }
        __syncthreads();
    }

    // final h (fp32) for the dense head
#pragma unroll
    for (int mt = 0; mt < 2; ++mt)
#pragma unroll
        for (int rp = 0; rp < 2; ++rp) {
            int row = m0 + wm * 32 + mt * 16 + lr + rp * 8;
            *(float2*)(g_h + (size_t)row * 512 + c0g) =
                make_float2(hprev[mt][rp][0], hprev[mt][rp][1]);
        }
}

// ---------------------------------------------------------------------------
// Dense head
// ---------------------------------------------------------------------------
__global__ void dense_kernel(const float* __restrict__ w,
                             const float* __restrict__ b0,
                             float* __restrict__ out)
{
    __shared__ float red[4];
    int b = blockIdx.x;
    int tid = threadIdx.x;
    const float* hrow = g_h + (size_t)b * Hh;

    float s = 0.0f;
    for (int n = tid; n < Hh; n += 128) s = fmaf(hrow[n], w[n], s);
#pragma unroll
    for (int o = 16; o > 0; o >>= 1) s += __shfl_down_sync(0xffffffffu, s, o);
    if ((tid & 31) == 0) red[tid >> 5] = s;
    __syncthreads();
    if (tid == 0) out[b] = red[0] + red[1] + red[2] + red[3] + b0[0];
}

// ---------------------------------------------------------------------------
// Launch
// ---------------------------------------------------------------------------
extern "C" void kernel_launch(void* const* d_in, const int* in_sizes, int n_in,
                              void* d_out, int out_size)
{
    const float* x       = (const float*)d_in[0];
    const float* kernel  = (const float*)d_in[1];
    const float* rkernel = (const float*)d_in[2];
    const float* bias_i  = (const float*)d_in[3];
    const float* bias_r  = (const float*)d_in[4];
    const float* dense_w = (const float*)d_in[5];
    const float* dense_b = (const float*)d_in[6];
    float* out = (float*)d_out;

    void *p_xh, *p_wt, *p_rt, *p_xproj;
    cudaGetSymbolAddress(&p_xh, g_xh);
    cudaGetSymbolAddress(&p_wt, g_wt);
    cudaGetSymbolAddress(&p_rt, g_rt);
    cudaGetSymbolAddress(&p_xproj, g_xproj);

    static bool attr_set = false;
    if (!attr_set) {
        cudaFuncSetAttribute(gru_persistent,
                             cudaFuncAttributeMaxDynamicSharedMemorySize, SMEM_PERSIST);
        cudaFuncSetAttribute(gemm_xproj,
                             cudaFuncAttributeMaxDynamicSharedMemorySize, XP_SMEM);
        attr_set = true;
    }

    prep_x_kernel<<<MBIG, 128>>>(x);
    prep_w_kernel<<<dim3(48, 16), dim3(32, 8)>>>(kernel,  (__half*)p_wt);
    prep_w_kernel<<<dim3(48, 16), dim3(32, 8)>>>(rkernel, (__half*)p_rt);

    gemm_xproj<<<dim3(G3c / 128, MBIG / 128), 256, XP_SMEM>>>(
        (const __half*)p_xh, (const __half*)p_wt, bias_i, (float*)p_xproj);

    gru_persistent<<<dim3(16, 8), 256, SMEM_PERSIST>>>(bias_r);

    dense_kernel<<<Bb, 128>>>(dense_w, dense_b, out);
}